// round 10
// baseline (speedup 1.0000x reference)
#include <cuda_runtime.h>
#include <cstdint>

// Problem constants (fixed by the reference)
#define NQ       64            // qubits
#define NS       4096          // samples per unique circuit
#define NU       256           // unique circuits
#define NB       1024          // batch size
#define PARTS    32            // blocks per circuit
#define NSB      (NS / PARTS)  // samples per block = 128
#define CHUNKS_B (NSB / 32)    // 4 chunks of 32 samples
#define THREADS  128
#define NWARPS   (THREADS / 32)          // 4 (one warp per chunk)
#define GRID     (NU * PARTS)  // 8192

// Per-(circuit,part) partial energy sums and completion counter.
__device__ __align__(16) float g_part[GRID];
__device__ unsigned int        g_count;   // zeroed; reset by last block

__device__ __forceinline__ void cp_async16(uint32_t saddr, const void* gptr)
{
    asm volatile("cp.async.cg.shared.global [%0], [%1], 16;"
                 :: "r"(saddr), "l"(gptr));
}

// One ballot-transpose step. Ballots act directly on the 0/1 int components.
// Lane owns qubits (lane) and (lane+32). Column bit order is a consistent
// permutation of sample order (irrelevant for XOR-popcount counting).
__device__ __forceinline__ void tstep(const uint4 v,
                                      const uint32_t b, const uint32_t p,
                                      uint32_t& colA, uint32_t& colB)
{
    const uint32_t W0 = __ballot_sync(0xffffffffu, v.x);
    const uint32_t W1 = __ballot_sync(0xffffffffu, v.y);
    const uint32_t W2 = __ballot_sync(0xffffffffu, v.z);
    const uint32_t W3 = __ballot_sync(0xffffffffu, v.w);
    const uint32_t Wl = (b & 1) ? W1 : W0;
    const uint32_t Wh = (b & 1) ? W3 : W2;
    const uint32_t Ws = (b & 2) ? Wh : Wl;
    const uint32_t t  = Ws >> p;
    colA = (colA << 2) | (t & 1u)        | ((t >> 15) & 2u);
    colB = (colB << 2) | ((t >> 8) & 1u) | ((t >> 23) & 2u);
}

// One block per (circuit, 1/32). Bulk cp.async stage of the whole block's
// raw data into smem -> transpose -> count. Memory overlap comes from ~6
// co-resident blocks per SM at independent phase positions.
__global__ void __launch_bounds__(THREADS)
energy_kernel(const int* __restrict__ samples,
              const int* __restrict__ idx,
              const float* __restrict__ bias,
              const float* __restrict__ kern,
              float* __restrict__ out)
{
    __shared__ uint4    raw[CHUNKS_B][512];   // 32 KB raw staged samples
    __shared__ uint32_t col[CHUNKS_B][NQ];    // 1 KB bit columns
    __shared__ float    red[NWARPS];
    __shared__ bool     s_last;

    const int tid  = threadIdx.x;
    const int lane = tid & 31;
    const int w    = tid >> 5;
    const int bx   = blockIdx.x;
    const int c    = bx >> 5;         // circuit
    const int part = bx & 31;         // 1/32 slice

    const uint4* base =
        (const uint4*)(samples + (size_t)c * (size_t)(NS * NQ))
        + (size_t)part * NSB * (NQ / 4);

    // ---------------- Stage: cp.async the block's 32 KB into smem ----------
    {
        const uint4* P = base + (size_t)w * 512;         // warp w -> chunk w
        uint32_t s0 = (uint32_t)__cvta_generic_to_shared(&raw[w][lane]);
        #pragma unroll
        for (int j = 0; j < 16; j++)
            cp_async16(s0 + (uint32_t)(j * 512), P + j * 32 + lane);
        asm volatile("cp.async.commit_group;");
        asm volatile("cp.async.wait_group 0;");
    }
    __syncthreads();

    // ---------------- Transpose: warp w -> chunk w --------------------------
    {
        const uint32_t b = lane & 3;
        const uint32_t p = lane >> 2;
        uint32_t colA = 0u, colB = 0u;
        #pragma unroll
        for (int j = 0; j < 16; j++)
            tstep(raw[w][j * 32 + lane], b, p, colA, colB);
        col[w][lane]      = colA;
        col[w][lane + 32] = colB;
    }
    __syncthreads();

    // ---------------- Count: triangular pair tiles --------------------------
    // Tile decode GUARDED (for t >= 136 the subtract loop diverges — the
    // R6/R8 5-ms regression).
    float acc = 0.f;

    // Primary tile for every thread (tid 0..127 all < 136).
    {
        int t = tid, I = 0;
        while (t >= 16 - I) { t -= 16 - I; I++; }
        const int J  = I + t;
        const int q0 = I << 2, r0 = J << 2;

        int cnt[4][4];
        #pragma unroll
        for (int i = 0; i < 4; i++)
            #pragma unroll
            for (int j = 0; j < 4; j++)
                cnt[i][j] = 0;

        #pragma unroll
        for (int ch = 0; ch < CHUNKS_B; ch++) {
            const uint4 a4 = *(const uint4*)&col[ch][q0];
            const uint4 b4 = *(const uint4*)&col[ch][r0];
            const uint32_t a[4]  = {a4.x, a4.y, a4.z, a4.w};
            const uint32_t bb[4] = {b4.x, b4.y, b4.z, b4.w};
            #pragma unroll
            for (int i = 0; i < 4; i++)
                #pragma unroll
                for (int j = 0; j < 4; j++)
                    cnt[i][j] += __popc(a[i] ^ bb[j]);
        }
        #pragma unroll
        for (int i = 0; i < 4; i++)
            #pragma unroll
            for (int j = 0; j < 4; j++) {
                const int q = q0 + i, r = r0 + j;
                float kv = kern[q * NQ + r];
                if (I != J) kv += kern[r * NQ + q];   // symmetry fold
                acc += kv * (float)(NSB - 2 * cnt[i][j]);
            }
    }

    // Secondary tiles 128..135 on threads 0..7 (deep diagonal, guarded).
    if (tid < 8) {
        int t = 128 + tid, I = 0;
        while (t >= 16 - I) { t -= 16 - I; I++; }
        const int J  = I + t;
        const int q0 = I << 2, r0 = J << 2;

        int cnt[4][4];
        #pragma unroll
        for (int i = 0; i < 4; i++)
            #pragma unroll
            for (int j = 0; j < 4; j++)
                cnt[i][j] = 0;

        #pragma unroll
        for (int ch = 0; ch < CHUNKS_B; ch++) {
            const uint4 a4 = *(const uint4*)&col[ch][q0];
            const uint4 b4 = *(const uint4*)&col[ch][r0];
            const uint32_t a[4]  = {a4.x, a4.y, a4.z, a4.w};
            const uint32_t bb[4] = {b4.x, b4.y, b4.z, b4.w};
            #pragma unroll
            for (int i = 0; i < 4; i++)
                #pragma unroll
                for (int j = 0; j < 4; j++)
                    cnt[i][j] += __popc(a[i] ^ bb[j]);
        }
        #pragma unroll
        for (int i = 0; i < 4; i++)
            #pragma unroll
            for (int j = 0; j < 4; j++) {
                const int q = q0 + i, r = r0 + j;
                float kv = kern[q * NQ + r];
                if (I != J) kv += kern[r * NQ + q];
                acc += kv * (float)(NSB - 2 * cnt[i][j]);
            }
    }

    // Linear term: threads 64..127, one qubit each.
    if (tid >= 64) {
        const int q = tid - 64;
        int n1 = 0;
        #pragma unroll
        for (int ch = 0; ch < CHUNKS_B; ch++)
            n1 += __popc(col[ch][q]);
        acc += bias[q] * (float)(NSB - 2 * n1);
    }

    // ---------------- Reduction + fused gather ----------------------------
    #pragma unroll
    for (int o = 16; o > 0; o >>= 1)
        acc += __shfl_down_sync(0xffffffffu, acc, o);
    if (lane == 0) red[w] = acc;
    __syncthreads();

    if (tid == 0) {
        g_part[bx] = red[0] + red[1] + red[2] + red[3];
        __threadfence();
        const unsigned int done = atomicAdd(&g_count, 1u);
        s_last = (done == GRID - 1);
    }
    __syncthreads();

    if (s_last) {
        __threadfence();
        for (int i = tid; i < NB; i += THREADS) {
            const int u = idx[i];
            const float4* gp = (const float4*)&g_part[u * PARTS];
            float s = 0.f;
            #pragma unroll
            for (int k = 0; k < PARTS / 4; k++) {
                const float4 v = gp[k];
                s += (v.x + v.y) + (v.z + v.w);
            }
            out[i] = s * (1.0f / (float)NS);
        }
        if (tid == 0) g_count = 0u;   // reset for next graph replay
    }
}

extern "C" void kernel_launch(void* const* d_in, const int* in_sizes, int n_in,
                              void* d_out, int out_size)
{
    const int*   samples = (const int*)d_in[0];
    const int*   idx     = (const int*)d_in[1];
    const float* bias    = (const float*)d_in[2];
    const float* kern    = (const float*)d_in[3];
    float*       out     = (float*)d_out;

    energy_kernel<<<GRID, THREADS>>>(samples, idx, bias, kern, out);
}

// round 11
// speedup vs baseline: 1.4860x; 1.4860x over previous
#include <cuda_runtime.h>
#include <cstdint>

// Problem constants (fixed by the reference)
#define NQ       64            // qubits
#define NS       4096          // samples per unique circuit
#define NU       256           // unique circuits
#define NB       1024          // batch size
#define PARTS    8             // blocks per circuit
#define NSB      (NS / PARTS)  // samples per block = 512
#define CHUNKS_B (NSB / 32)    // 16 chunks of 32 samples
#define THREADS  256
#define NWARPS   (THREADS / 32)
#define CH_PER_WARP (CHUNKS_B / NWARPS)  // 2
#define GRID     (NU * PARTS)  // 2048
#define WAVE     592           // 148 SMs x 4 resident blocks: one wave

// Per-(circuit,part) partial energy sums and completion counter.
__device__ float        g_part[GRID];
__device__ unsigned int g_count;   // zero-initialized; reset by last block

// One ballot-transpose step. Ballots act DIRECTLY on the 0/1 int components
// (predicate = nonzero). Lane owns qubits (lane) and (lane+32). Column bit
// order is a consistent permutation of sample order, which is irrelevant
// for XOR-popcount pair counting and column popcounts.
__device__ __forceinline__ void tstep(const uint4 v, const uint32_t b,
                                      const uint32_t p,
                                      uint32_t& colA, uint32_t& colB)
{
    const uint32_t W0 = __ballot_sync(0xffffffffu, v.x);
    const uint32_t W1 = __ballot_sync(0xffffffffu, v.y);
    const uint32_t W2 = __ballot_sync(0xffffffffu, v.z);
    const uint32_t W3 = __ballot_sync(0xffffffffu, v.w);
    const uint32_t Wl = (b & 1) ? W1 : W0;
    const uint32_t Wh = (b & 1) ? W3 : W2;
    const uint32_t Ws = (b & 2) ? Wh : Wl;
    const uint32_t t  = Ws >> p;
    // qubit lane: t bits 0,16 ; qubit lane+32: t bits 8,24.
    colA = (colA << 2) | (t & 1u)        | ((t >> 15) & 2u);
    colB = (colB << 2) | ((t >> 8) & 1u) | ((t >> 23) & 2u);
}

// One block per (circuit, eighth) — the R7 champion structure, plus a
// cross-wave L2 prefetch: during this block's loads-idle compute phase it
// prefetches the ENTIRE 128 KB working set of block (bx + WAVE), which will
// occupy this SM slot one wave later. L2 is chip-shared, the prefetch costs
// no registers and no smem, and it keeps DRAM busy through the popcount
// phase. Budget: 592 x 128 KB = 75 MB < 126 MB L2.
__global__ void __launch_bounds__(THREADS)
energy_kernel(const int* __restrict__ samples,
              const int* __restrict__ idx,
              const float* __restrict__ bias,
              const float* __restrict__ kern,
              float* __restrict__ out)
{
    __shared__ uint32_t col[CHUNKS_B][NQ];   // 4 KB
    __shared__ float red[NWARPS];
    __shared__ bool s_last;

    const int tid  = threadIdx.x;
    const int lane = tid & 31;
    const int w    = tid >> 5;
    const int bx   = blockIdx.x;

    // Block bx's data: items are contiguous 128 KB slabs (8192 uint4).
    const uint4* base = (const uint4*)samples + (size_t)bx * 8192;

    const uint32_t b = lane & 3;     // bit index within nibble
    const uint32_t p = lane >> 2;    // qubit group

    // ---------------- Phase 1: batched streaming loads + transpose ---------
    #pragma unroll
    for (int k = 0; k < CH_PER_WARP; k++) {
        const int ch = w * CH_PER_WARP + k;
        const uint4* P = base + (size_t)ch * 512;   // 32 rows * 16 uint4

        uint32_t colA = 0u, colB = 0u;
        uint4 v[8];

        #pragma unroll
        for (int j = 0; j < 8; j++)
            v[j] = __ldcs(&P[j * 32 + lane]);        // streaming, MLP=8
        #pragma unroll
        for (int j = 0; j < 8; j++)
            tstep(v[j], b, p, colA, colB);

        #pragma unroll
        for (int j = 0; j < 8; j++)
            v[j] = __ldcs(&P[(j + 8) * 32 + lane]);  // streaming, MLP=8
        #pragma unroll
        for (int j = 0; j < 8; j++)
            tstep(v[j], b, p, colA, colB);

        col[ch][lane]      = colA;
        col[ch][lane + 32] = colB;
    }
    __syncthreads();

    // ---------------- Cross-wave L2 prefetch (loads-idle phase) ------------
    if (bx + WAVE < GRID) {
        const char* np = (const char*)((const uint4*)samples
                                       + (size_t)(bx + WAVE) * 8192);
        #pragma unroll
        for (int k2 = 0; k2 < 4; k2++)
            asm volatile("prefetch.global.L2 [%0];"
                         :: "l"(np + (size_t)(tid + 256 * k2) * 128));
    }

    // ---------------- Phase 2: triangular pair counting --------------------
    float acc = 0.f;

    if (tid < 136) {
        // tid -> upper-triangle tile (I <= J) of the 16x16 tile grid.
        // GUARDED decode (unguarded it diverges for tid >= 136 — the R6/R8
        // 5-ms regression).
        int t = tid, I = 0;
        while (t >= 16 - I) { t -= 16 - I; I++; }
        const int J  = I + t;
        const int q0 = I << 2;
        const int r0 = J << 2;

        int cnt[4][4];
        #pragma unroll
        for (int i = 0; i < 4; i++)
            #pragma unroll
            for (int j = 0; j < 4; j++)
                cnt[i][j] = 0;

        #pragma unroll 4
        for (int ch = 0; ch < CHUNKS_B; ch++) {
            const uint4 a4 = *(const uint4*)&col[ch][q0];
            const uint4 b4 = *(const uint4*)&col[ch][r0];
            const uint32_t a[4]  = {a4.x, a4.y, a4.z, a4.w};
            const uint32_t bb[4] = {b4.x, b4.y, b4.z, b4.w};
            #pragma unroll
            for (int i = 0; i < 4; i++)
                #pragma unroll
                for (int j = 0; j < 4; j++)
                    cnt[i][j] += __popc(a[i] ^ bb[j]);
        }

        // Fold K: off-diagonal tiles cover (q,r) and (r,q) via symmetry.
        #pragma unroll
        for (int i = 0; i < 4; i++) {
            #pragma unroll
            for (int j = 0; j < 4; j++) {
                const int q = q0 + i, r = r0 + j;
                float kv = kern[q * NQ + r];
                if (I != J) kv += kern[r * NQ + q];
                acc += kv * (float)(NSB - 2 * cnt[i][j]);
            }
        }
    }

    // Linear term on otherwise-idle warps 6,7.
    if (tid >= 192) {
        const int q = tid - 192;
        int n1 = 0;
        #pragma unroll
        for (int ch = 0; ch < CHUNKS_B; ch++)
            n1 += __popc(col[ch][q]);
        acc += bias[q] * (float)(NSB - 2 * n1);
    }

    // ---------------- Reduction + fused gather ----------------------------
    #pragma unroll
    for (int o = 16; o > 0; o >>= 1)
        acc += __shfl_down_sync(0xffffffffu, acc, o);
    if (lane == 0) red[w] = acc;
    __syncthreads();

    if (tid == 0) {
        float s = 0.f;
        #pragma unroll
        for (int i = 0; i < NWARPS; i++) s += red[i];
        g_part[bx] = s;
        __threadfence();
        const unsigned int done = atomicAdd(&g_count, 1u);
        s_last = (done == GRID - 1);
    }
    __syncthreads();

    if (s_last) {
        __threadfence();
        for (int i = tid; i < NB; i += THREADS) {
            const int u = idx[i];
            const float* gp = &g_part[u * PARTS];
            float s = 0.f;
            #pragma unroll
            for (int q = 0; q < PARTS; q++) s += gp[q];
            out[i] = s * (1.0f / (float)NS);
        }
        if (tid == 0) g_count = 0u;   // reset for next graph replay
    }
}

extern "C" void kernel_launch(void* const* d_in, const int* in_sizes, int n_in,
                              void* d_out, int out_size)
{
    const int*   samples = (const int*)d_in[0];
    const int*   idx     = (const int*)d_in[1];
    const float* bias    = (const float*)d_in[2];
    const float* kern    = (const float*)d_in[3];
    float*       out     = (float*)d_out;

    energy_kernel<<<GRID, THREADS>>>(samples, idx, bias, kern, out);
}